// round 8
// baseline (speedup 1.0000x reference)
#include <cuda_runtime.h>
#include <cuda_fp16.h>
#include <math.h>
#include <stdint.h>

#define NB 4
#define NC 512
#define NT 1024
#define NHEADS 8
#define NHD 64
#define EPS_IN 1e-5f
#define CH 64
#define QB 16

// ---------------- device scratch ----------------
__device__ __half g_w16[4 * NC * NC];                      // wq,wk,wv,wproj fp16
__device__ __half g_xT[NB * NT * NC];                      // x transposed [b][t][c]
__device__ __half g_qT[NB * NT * NC];
__device__ __half g_kT[NB * NT * NC];
__device__ __half g_vh[NB * NC * NT];                      // v [b][c][t]
__device__ float g_attn[(size_t)NB * NHEADS * NT * NT];    // raw logits fp32 134MB
__device__ float g_oacc[NB * NHEADS * NT * NHD];           // unnormalized PV accum
__device__ float g_l[NB * NHEADS * NT];                    // softmax denominators
__device__ __half g_outh[NB * NHEADS * NT * NHD];          // mid, flat == [b][t][c]
__device__ float g_vsum[NB * NC];
__device__ float g_rowsq[NB * NHEADS * NT];
__device__ float g_alpha[32];
__device__ float g_betac[32];

__device__ __forceinline__ void mma16h(float* c, const uint32_t* a, const uint32_t* b) {
    asm volatile("mma.sync.aligned.m16n8k16.row.col.f32.f16.f16.f32 "
        "{%0,%1,%2,%3}, {%4,%5,%6,%7}, {%8,%9}, {%0,%1,%2,%3};\n"
        : "+f"(c[0]), "+f"(c[1]), "+f"(c[2]), "+f"(c[3])
        : "r"(a[0]), "r"(a[1]), "r"(a[2]), "r"(a[3]), "r"(b[0]), "r"(b[1]));
}

// ============ prep: weights -> fp16 ============
__global__ __launch_bounds__(256) void prep_w(const float* __restrict__ wq,
                                              const float* __restrict__ wk,
                                              const float* __restrict__ wv,
                                              const float* __restrict__ wp) {
    int idx = blockIdx.x * 256 + threadIdx.x;
    int which = idx >> 18, off = idx & 262143;
    const float* s = (which == 0) ? wq : (which == 1) ? wk : (which == 2) ? wv : wp;
    g_w16[idx] = __float2half(s[off]);
}

// ============ prep: xT[b][t][c] fp16 ============
__global__ __launch_bounds__(256) void prep_x(const float* __restrict__ x) {
    __shared__ float tile[32][33];
    int tx = threadIdx.x, ty = threadIdx.y;
    int tBase = blockIdx.x * 32, cBase = blockIdx.y * 32, b = blockIdx.z;
    const float* X = x + (size_t)b * NC * NT;
#pragma unroll
    for (int p = 0; p < 4; p++)
        tile[ty + 8 * p][tx] = X[(size_t)(cBase + ty + 8 * p) * NT + tBase + tx];
    __syncthreads();
    __half* dst = g_xT + (size_t)b * NT * NC;
#pragma unroll
    for (int p = 0; p < 4; p++)
        dst[(size_t)(tBase + ty + 8 * p) * NC + cBase + tx] = __float2half(tile[tx][ty + 8 * p]);
}

// ============ Kernel 1: QKV fp16 ============
__global__ __launch_bounds__(256) void qkv_f16() {
    int z = blockIdx.z;
    int b = z / 3, which = z - b * 3;
    const __half* W = g_w16 + (size_t)which * NC * NC;
    const __half* X = g_xT + (size_t)b * NT * NC;

    int oBase = blockIdx.y * 128;
    int tBase = blockIdx.x * 128;

    __shared__ union {
        struct { uint32_t A[128][20]; uint32_t B[128][20]; } ab;
        unsigned short st[128][136];
    } smu;

    int tid = threadIdx.x, lane = tid & 31, wid = tid >> 5;
    int wm = wid >> 2, wn = wid & 3;
    int lr = lane >> 2, lk = lane & 3;

    float acc[4][4][4];
#pragma unroll
    for (int mi = 0; mi < 4; mi++)
#pragma unroll
        for (int nj = 0; nj < 4; nj++)
#pragma unroll
            for (int ci = 0; ci < 4; ci++) acc[mi][nj][ci] = 0.f;

    for (int k0 = 0; k0 < NC; k0 += 32) {
#pragma unroll
        for (int i = 0; i < 2; i++) {
            int idx = tid + i * 256;
            int row = idx >> 2, uu = idx & 3;
            *(uint4*)&smu.ab.A[row][uu * 4] =
                *(const uint4*)&W[(size_t)(oBase + row) * NC + k0 + uu * 8];
            *(uint4*)&smu.ab.B[row][uu * 4] =
                *(const uint4*)&X[(size_t)(tBase + row) * NC + k0 + uu * 8];
        }
        __syncthreads();
#pragma unroll
        for (int ci = 0; ci < 2; ci++) {
            int kc = ci * 8;
            uint32_t af[4][4], bf[4][2];
#pragma unroll
            for (int mi = 0; mi < 4; mi++) {
                int m0 = wm * 64 + mi * 16 + lr;
                af[mi][0] = smu.ab.A[m0][kc + lk];
                af[mi][1] = smu.ab.A[m0 + 8][kc + lk];
                af[mi][2] = smu.ab.A[m0][kc + lk + 4];
                af[mi][3] = smu.ab.A[m0 + 8][kc + lk + 4];
            }
#pragma unroll
            for (int nj = 0; nj < 4; nj++) {
                int n0 = wn * 32 + nj * 8 + lr;
                bf[nj][0] = smu.ab.B[n0][kc + lk];
                bf[nj][1] = smu.ab.B[n0][kc + lk + 4];
            }
#pragma unroll
            for (int mi = 0; mi < 4; mi++)
#pragma unroll
                for (int nj = 0; nj < 4; nj++) mma16h(acc[mi][nj], af[mi], bf[nj]);
        }
        __syncthreads();
    }

    if (which == 2) {
        __half* vh = g_vh + (size_t)b * NC * NT;
#pragma unroll
        for (int mi = 0; mi < 4; mi++) {
            int r = oBase + wm * 64 + mi * 16 + lr;
#pragma unroll
            for (int nj = 0; nj < 4; nj++) {
                int cc = tBase + wn * 32 + nj * 8 + lk * 2;
                *(__half2*)&vh[(size_t)r * NT + cc] =
                    __floats2half2_rn(acc[mi][nj][0], acc[mi][nj][1]);
                *(__half2*)&vh[(size_t)(r + 8) * NT + cc] =
                    __floats2half2_rn(acc[mi][nj][2], acc[mi][nj][3]);
            }
        }
    } else {
        __half* dst = ((which == 0) ? g_qT : g_kT) + (size_t)b * NT * NC;
#pragma unroll
        for (int mi = 0; mi < 4; mi++) {
            int r = wm * 64 + mi * 16 + lr;
#pragma unroll
            for (int nj = 0; nj < 4; nj++) {
                int cc = wn * 32 + nj * 8 + lk * 2;
                smu.st[cc][r]         = __half_as_ushort(__float2half(acc[mi][nj][0]));
                smu.st[cc + 1][r]     = __half_as_ushort(__float2half(acc[mi][nj][1]));
                smu.st[cc][r + 8]     = __half_as_ushort(__float2half(acc[mi][nj][2]));
                smu.st[cc + 1][r + 8] = __half_as_ushort(__float2half(acc[mi][nj][3]));
            }
        }
        __syncthreads();
        int row = tid >> 1, ub = (tid & 1) * 8;
#pragma unroll
        for (int j = 0; j < 8; j++) {
            *(uint4*)&dst[(size_t)(tBase + row) * NC + oBase + (ub + j) * 8] =
                *(const uint4*)&smu.st[row][(ub + j) * 8];
        }
    }
}

// ============ Kernel 2: QK^T fp16 -> fp32 raw logits ============
__global__ __launch_bounds__(256) void qk_f16() {
    int bh = blockIdx.z;
    int b = bh >> 3, h = bh & 7;
    const __half* Aq = g_qT + (size_t)b * NT * NC;
    const __half* Bk = g_kT + (size_t)b * NT * NC;
    float* out = g_attn + (size_t)bh * NT * NT;

    int qBase = blockIdx.y * 128;
    int tBase = blockIdx.x * 128;

    __shared__ uint32_t As[128][36];
    __shared__ uint32_t Bs[128][36];

    int tid = threadIdx.x, lane = tid & 31, wid = tid >> 5;
    int wm = wid >> 2, wn = wid & 3;
    int lr = lane >> 2, lk = lane & 3;

#pragma unroll
    for (int i = 0; i < 4; i++) {
        int idx = tid + i * 256;
        int row = idx >> 3, uu = idx & 7;
        *(uint4*)&As[row][uu * 4] =
            *(const uint4*)&Aq[(size_t)(qBase + row) * NC + h * 64 + uu * 8];
        *(uint4*)&Bs[row][uu * 4] =
            *(const uint4*)&Bk[(size_t)(tBase + row) * NC + h * 64 + uu * 8];
    }
    __syncthreads();

    float acc[4][4][4];
#pragma unroll
    for (int mi = 0; mi < 4; mi++)
#pragma unroll
        for (int nj = 0; nj < 4; nj++)
#pragma unroll
            for (int ci = 0; ci < 4; ci++) acc[mi][nj][ci] = 0.f;

#pragma unroll
    for (int ci = 0; ci < 4; ci++) {
        int kc = ci * 8;
        uint32_t af[4][4], bf[4][2];
#pragma unroll
        for (int mi = 0; mi < 4; mi++) {
            int m0 = wm * 64 + mi * 16 + lr;
            af[mi][0] = As[m0][kc + lk];
            af[mi][1] = As[m0 + 8][kc + lk];
            af[mi][2] = As[m0][kc + lk + 4];
            af[mi][3] = As[m0 + 8][kc + lk + 4];
        }
#pragma unroll
        for (int nj = 0; nj < 4; nj++) {
            int n0 = wn * 32 + nj * 8 + lr;
            bf[nj][0] = Bs[n0][kc + lk];
            bf[nj][1] = Bs[n0][kc + lk + 4];
        }
#pragma unroll
        for (int mi = 0; mi < 4; mi++)
#pragma unroll
            for (int nj = 0; nj < 4; nj++) mma16h(acc[mi][nj], af[mi], bf[nj]);
    }

#pragma unroll
    for (int mi = 0; mi < 4; mi++) {
        int r = qBase + wm * 64 + mi * 16 + lr;
#pragma unroll
        for (int nj = 0; nj < 4; nj++) {
            int cc = tBase + wn * 32 + nj * 8 + lk * 2;
            *(float2*)&out[(size_t)r * NT + cc] =
                make_float2(acc[mi][nj][0] * 0.125f, acc[mi][nj][1] * 0.125f);
            *(float2*)&out[(size_t)(r + 8) * NT + cc] =
                make_float2(acc[mi][nj][2] * 0.125f, acc[mi][nj][3] * 0.125f);
        }
    }
}

// ============ Kernel 3: fused mix + online softmax + AV (flash-style) ============
// Block = (b, 16 q rows). Streams T chunks of 64. Never materializes probs.
__global__ __launch_bounds__(256, 2) void msoav(const float* __restrict__ w_head) {
    extern __shared__ char smc[];
    float* whs = (float*)smc;                          // 64
    float* Ss  = whs + 64;                             // 8*16 scale factors
    __half* Ps = (__half*)(Ss + 128);                  // [8][16][72]
    __half* Vs = Ps + 8 * 16 * 72;                     // [512][72]

    int b = 3 - (int)blockIdx.y;                       // reverse for L2 reuse
    int qBase = (gridDim.x - 1 - blockIdx.x) * QB;

    int tid = threadIdx.x, lane = tid & 31, wid = tid >> 5;
    int qloc = tid >> 4, l16 = tid & 15;
    int lr = lane >> 2, lk = lane & 3;

    if (tid < 64) whs[tid] = w_head[tid];
    __syncthreads();

    float m[8], l[8], s2[8];
#pragma unroll
    for (int g = 0; g < 8; g++) { m[g] = -1e30f; l[g] = 0.f; s2[g] = 0.f; }

    float acc[8][4];   // PV accum: this warp's g, 8 n-tiles
#pragma unroll
    for (int nj = 0; nj < 8; nj++)
#pragma unroll
        for (int ci = 0; ci < 4; ci++) acc[nj][ci] = 0.f;

    const float* attnB = g_attn + (size_t)b * 8 * NT * NT + (size_t)qBase * NT;
    const __half* vB = g_vh + (size_t)b * NC * NT;

    for (int c0 = 0; c0 < NT; c0 += CH) {
        // ---- stage V chunk [512 ch][64 T] into smem ----
#pragma unroll
        for (int i = 0; i < 16; i++) {
            int idx = tid + i * 256;
            int ch = idx >> 3, seg = idx & 7;
            *(uint4*)&Vs[ch * 72 + seg * 8] =
                *(const uint4*)&vB[(size_t)ch * NT + c0 + seg * 8];
        }
        // ---- phase 1: load raw logits (8 heads), mix, online softmax ----
        float4 rv[8];
#pragma unroll
        for (int h = 0; h < 8; h++)
            rv[h] = *(const float4*)&attnB[(size_t)h * NT * NT + (size_t)qloc * NT + c0 + l16 * 4];

#pragma unroll
        for (int g = 0; g < 8; g++) {
            float mg0 = 0.f, mg1 = 0.f, mg2 = 0.f, mg3 = 0.f;
#pragma unroll
            for (int h = 0; h < 8; h++) {
                float w = whs[g * 8 + h];
                mg0 += w * rv[h].x; mg1 += w * rv[h].y;
                mg2 += w * rv[h].z; mg3 += w * rv[h].w;
            }
            float cm = fmaxf(fmaxf(mg0, mg1), fmaxf(mg2, mg3));
            cm = fmaxf(cm, __shfl_xor_sync(0xffffffffu, cm, 8));
            cm = fmaxf(cm, __shfl_xor_sync(0xffffffffu, cm, 4));
            cm = fmaxf(cm, __shfl_xor_sync(0xffffffffu, cm, 2));
            cm = fmaxf(cm, __shfl_xor_sync(0xffffffffu, cm, 1));
            float nm = fmaxf(m[g], cm);
            float sc = __expf(m[g] - nm);
            m[g] = nm;
            float e0 = __expf(mg0 - nm), e1 = __expf(mg1 - nm);
            float e2 = __expf(mg2 - nm), e3 = __expf(mg3 - nm);
            float cl = (e0 + e1) + (e2 + e3);
            float cq = (e0 * e0 + e1 * e1) + (e2 * e2 + e3 * e3);
            cl += __shfl_xor_sync(0xffffffffu, cl, 8);
            cq += __shfl_xor_sync(0xffffffffu, cq, 8);
            cl += __shfl_xor_sync(0xffffffffu, cl, 4);
            cq += __shfl_xor_sync(0xffffffffu, cq, 4);
            cl += __shfl_xor_sync(0xffffffffu, cl, 2);
            cq += __shfl_xor_sync(0xffffffffu, cq, 2);
            cl += __shfl_xor_sync(0xffffffffu, cl, 1);
            cq += __shfl_xor_sync(0xffffffffu, cq, 1);
            l[g] = l[g] * sc + cl;
            s2[g] = s2[g] * sc * sc + cq;
            if (l16 == 0) Ss[g * 16 + qloc] = sc;
            __half2 p0 = __floats2half2_rn(e0, e1);
            __half2 p1 = __floats2half2_rn(e2, e3);
            uint2 u;
            u.x = *(uint32_t*)&p0;
            u.y = *(uint32_t*)&p1;
            *(uint2*)&Ps[(g * 16 + qloc) * 72 + l16 * 4] = u;
        }
        __syncthreads();

        // ---- phase 2: warp g does P_g @ V_g^T with flash rescale ----
        {
            int g = wid;
            float sA = Ss[g * 16 + lr];
            float sB = Ss[g * 16 + lr + 8];
#pragma unroll
            for (int nj = 0; nj < 8; nj++) {
                acc[nj][0] *= sA; acc[nj][1] *= sA;
                acc[nj][2] *= sB; acc[nj][3] *= sB;
            }
            const __half* Pg = Ps + g * 16 * 72;
            const __half* Vg = Vs + g * 64 * 72;
#pragma unroll
            for (int ks = 0; ks < 4; ks++) {
                int kb = ks * 16 + lk * 2;
                uint32_t af[4];
                af[0] = *(const uint32_t*)&Pg[lr * 72 + kb];
                af[1] = *(const uint32_t*)&Pg[(lr + 8) * 72 + kb];
                af[2] = *(const uint32_t*)&Pg[lr * 72 + kb + 8];
                af[3] = *(const uint32_t*)&Pg[(lr + 8) * 72 + kb + 8];
#pragma unroll
                for (int nj = 0; nj < 8; nj++) {
                    uint32_t bf[2];
                    bf[0] = *(const uint32_t*)&Vg[(nj * 8 + lr) * 72 + kb];
                    bf[1] = *(const uint32_t*)&Vg[(nj * 8 + lr) * 72 + kb + 8];
                    mma16h(acc[nj], af, bf);
                }
            }
        }
        __syncthreads();
    }

    // ---- epilogue: write unnormalized O, l, rowsq ----
    {
        int g = wid;
        float* Op = g_oacc + ((size_t)(b * 8 + g) * NT + qBase) * NHD;
#pragma unroll
        for (int nj = 0; nj < 8; nj++) {
            int d0 = nj * 8 + lk * 2;
            *(float2*)&Op[(size_t)lr * NHD + d0] = make_float2(acc[nj][0], acc[nj][1]);
            *(float2*)&Op[(size_t)(lr + 8) * NHD + d0] = make_float2(acc[nj][2], acc[nj][3]);
        }
    }
    if (l16 == 0) {
#pragma unroll
        for (int g = 0; g < 8; g++) {
            int r = (b * 8 + g) * NT + qBase + qloc;
            g_l[r] = l[g];
            g_rowsq[r] = s2[g] / (l[g] * l[g]);
        }
    }
}

// ============ Kernel 4: vsum from fp16 v ============
__global__ __launch_bounds__(256) void vsum_f16() {
    __shared__ float sbuf[8];
    int row = blockIdx.x;
    const __half2* p = (const __half2*)(g_vh + (size_t)row * NT) + threadIdx.x * 2;
    float2 a = __half22float2(p[0]);
    float2 bb = __half22float2(p[1]);
    float s = (a.x + a.y) + (bb.x + bb.y);
    int lane = threadIdx.x & 31, w = threadIdx.x >> 5;
#pragma unroll
    for (int o = 16; o > 0; o >>= 1) s += __shfl_xor_sync(0xffffffffu, s, o);
    if (lane == 0) sbuf[w] = s;
    __syncthreads();
    if (threadIdx.x == 0) {
        float tt = 0.f;
        for (int i = 0; i < 8; i++) tt += sbuf[i];
        g_vsum[row] = tt;
    }
}

// ============ Kernel 5: finalize InstanceNorm params ============
__global__ __launch_bounds__(256) void finalize_kernel(const float* __restrict__ gamma,
                                                       const float* __restrict__ beta) {
    __shared__ float sbuf[8];
    int grp = blockIdx.x;
    float s = 0.f;
    for (int i = threadIdx.x; i < NT; i += 256) s += g_rowsq[grp * NT + i];
    int lane = threadIdx.x & 31, w = threadIdx.x >> 5;
#pragma unroll
    for (int o = 16; o > 0; o >>= 1) s += __shfl_xor_sync(0xffffffffu, s, o);
    if (lane == 0) sbuf[w] = s;
    __syncthreads();
    if (threadIdx.x == 0) {
        float sumsq = 0.f;
        for (int i = 0; i < 8; i++) sumsq += sbuf[i];
        const float invN = 1.f / (1024.f * 1024.f);
        float mean = 1.f / 1024.f;
        float var = sumsq * invN - mean * mean;
        int h = grp & 7;
        float alpha = gamma[h] * rsqrtf(var + EPS_IN);
        g_alpha[grp] = alpha;
        g_betac[grp] = beta[h] - alpha * mean;
    }
}

// ============ Kernel 6: normalize O + InstanceNorm fold -> fp16 mid ============
__global__ __launch_bounds__(256) void o_epilogue() {
    int bh = blockIdx.y;
    int qt = blockIdx.x;   // 16 tiles of 64 q
    float alpha = g_alpha[bh], bc = g_betac[bh];
    size_t base = (size_t)bh * NT * NHD + (size_t)qt * 64 * NHD;
#pragma unroll
    for (int i = 0; i < 4; i++) {
        int e4 = threadIdx.x + i * 256;    // 1024 float4 groups
        int q = qt * 64 + (e4 >> 4);
        int d = (e4 & 15) * 4;
        float4 o = *(const float4*)&g_oacc[base + (size_t)(e4 >> 4) * NHD + d];
        float invl = 1.f / g_l[bh * NT + q];
        float4 vs = *(const float4*)&g_vsum[bh * NHD + d];
        __half2 h0 = __floats2half2_rn(alpha * o.x * invl + bc * vs.x,
                                       alpha * o.y * invl + bc * vs.y);
        __half2 h1 = __floats2half2_rn(alpha * o.z * invl + bc * vs.z,
                                       alpha * o.w * invl + bc * vs.w);
        uint2 u;
        u.x = *(uint32_t*)&h0;
        u.y = *(uint32_t*)&h1;
        *(uint2*)&g_outh[base + (size_t)(e4 >> 4) * NHD + d] = u;
    }
}

// ============ Kernel 7: projection fp16 ============
__global__ __launch_bounds__(256) void proj_f16(const float* __restrict__ b_proj,
                                                float* __restrict__ outF) {
    int b = blockIdx.z;
    int coBase = blockIdx.y * 128;
    int tBase = blockIdx.x * 128;
    const __half* W = g_w16 + (size_t)3 * NC * NC;
    const __half* M = g_outh + (size_t)b * NT * NC;

    __shared__ uint32_t As[128][20];
    __shared__ uint32_t Bs[128][20];

    int tid = threadIdx.x, lane = tid & 31, wid = tid >> 5;
    int wm = wid >> 2, wn = wid & 3;
    int lr = lane >> 2, lk = lane & 3;

    float acc[4][4][4];
#pragma unroll
    for (int mi = 0; mi < 4; mi++)
#pragma unroll
        for (int nj = 0; nj < 4; nj++)
#pragma unroll
            for (int ci = 0; ci < 4; ci++) acc[mi][nj][ci] = 0.f;

    for (int k0 = 0; k0 < NC; k0 += 32) {
#pragma unroll
        for (int i = 0; i < 2; i++) {
            int idx = tid + i * 256;
            int row = idx >> 2, uu = idx & 3;
            *(uint4*)&As[row][uu * 4] =
                *(const uint4*)&W[(size_t)(coBase + row) * NC + k0 + uu * 8];
            *(uint4*)&Bs[row][uu * 4] =
                *(const uint4*)&M[(size_t)(tBase + row) * NC + k0 + uu * 8];
        }
        __syncthreads();
#pragma unroll
        for (int ci = 0; ci < 2; ci++) {
            int kc = ci * 8;
            uint32_t af[4][4], bf[4][2];
#pragma unroll
            for (int mi = 0; mi < 4; mi++) {
                int m0 = wm * 64 + mi * 16 + lr;
                af[mi][0] = As[m0][kc + lk];
                af[mi][1] = As[m0 + 8][kc + lk];
                af[mi][2] = As[m0][kc + lk + 4];
                af[mi][3] = As[m0 + 8][kc + lk + 4];
            }
#pragma unroll
            for (int nj = 0; nj < 4; nj++) {
                int n0 = wn * 32 + nj * 8 + lr;
                bf[nj][0] = Bs[n0][kc + lk];
                bf[nj][1] = Bs[n0][kc + lk + 4];
            }
#pragma unroll
            for (int mi = 0; mi < 4; mi++)
#pragma unroll
                for (int nj = 0; nj < 4; nj++) mma16h(acc[mi][nj], af[mi], bf[nj]);
        }
        __syncthreads();
    }
#pragma unroll
    for (int mi = 0; mi < 4; mi++) {
        int co = coBase + wm * 64 + mi * 16 + lr;
        float bias0 = b_proj[co], bias1 = b_proj[co + 8];
        float* op0 = outF + (size_t)b * NC * NT + (size_t)co * NT;
        float* op1 = op0 + (size_t)8 * NT;
#pragma unroll
        for (int nj = 0; nj < 4; nj++) {
            int cc = tBase + wn * 32 + nj * 8 + lk * 2;
            *(float2*)&op0[cc] = make_float2(acc[mi][nj][0] + bias0, acc[mi][nj][1] + bias0);
            *(float2*)&op1[cc] = make_float2(acc[mi][nj][2] + bias1, acc[mi][nj][3] + bias1);
        }
    }
}

// ---------------- launch ----------------
extern "C" void kernel_launch(void* const* d_in, const int* in_sizes, int n_in,
                              void* d_out, int out_size) {
    (void)in_sizes; (void)n_in; (void)out_size;
    const float* x        = (const float*)d_in[0];
    const float* w_q      = (const float*)d_in[1];
    const float* w_k      = (const float*)d_in[2];
    const float* w_v      = (const float*)d_in[3];
    const float* w_head   = (const float*)d_in[4];
    const float* in_gamma = (const float*)d_in[5];
    const float* in_beta  = (const float*)d_in[6];
    const float* w_proj   = (const float*)d_in[7];
    const float* b_proj   = (const float*)d_in[8];
    float* outF = (float*)d_out;

    const int MSOAV_SMEM = (64 + 128) * 4 + (8 * 16 * 72 + 512 * 72) * 2;  // 92928
    cudaFuncSetAttribute(msoav, cudaFuncAttributeMaxDynamicSharedMemorySize, MSOAV_SMEM);

    prep_w<<<4096, 256>>>(w_q, w_k, w_v, w_proj);
    prep_x<<<dim3(32, 16, 4), dim3(32, 8)>>>(x);
    qkv_f16<<<dim3(8, 4, 12), 256>>>();
    qk_f16<<<dim3(8, 8, 32), 256>>>();
    vsum_f16<<<2048, 256>>>();
    msoav<<<dim3(64, 4), 256, MSOAV_SMEM>>>(w_head);
    finalize_kernel<<<32, 256>>>(in_gamma, in_beta);
    o_epilogue<<<dim3(16, 32), 256>>>();
    proj_f16<<<dim3(8, 4, 4), 256>>>(b_proj, outF);
}

// round 9
// speedup vs baseline: 1.0016x; 1.0016x over previous
#include <cuda_runtime.h>
#include <cuda_fp16.h>
#include <math.h>
#include <stdint.h>

#define NB 4
#define NC 512
#define NT 1024
#define NHEADS 8
#define NHD 64
#define EPS_IN 1e-5f
#define CH 64
#define QB 16

// ---------------- device scratch ----------------
__device__ __half g_w16[4 * NC * NC];                      // wq,wk,wv,wproj fp16
__device__ __half g_xT[NB * NT * NC];                      // x transposed [b][t][c]
__device__ __half g_qT[NB * NT * NC];
__device__ __half g_kT[NB * NT * NC];
__device__ __half g_vh[NB * NC * NT];                      // v [b][c][t]
__device__ float g_attn[(size_t)NB * NHEADS * NT * NT];    // raw logits fp32 134MB
__device__ float g_oacc[NB * NHEADS * NT * NHD];           // unnormalized PV accum
__device__ float g_l[NB * NHEADS * NT];                    // softmax denominators
__device__ __half g_outh[NB * NHEADS * NT * NHD];          // mid, flat == [b][t][c]
__device__ float g_vsum[NB * NC];
__device__ float g_rowsq[NB * NHEADS * NT];
__device__ float g_alpha[32];
__device__ float g_betac[32];

__device__ __forceinline__ void mma16h(float* c, const uint32_t* a, const uint32_t* b) {
    asm volatile("mma.sync.aligned.m16n8k16.row.col.f32.f16.f16.f32 "
        "{%0,%1,%2,%3}, {%4,%5,%6,%7}, {%8,%9}, {%0,%1,%2,%3};\n"
        : "+f"(c[0]), "+f"(c[1]), "+f"(c[2]), "+f"(c[3])
        : "r"(a[0]), "r"(a[1]), "r"(a[2]), "r"(a[3]), "r"(b[0]), "r"(b[1]));
}

// ============ prep: weights -> fp16 ============
__global__ __launch_bounds__(256) void prep_w(const float* __restrict__ wq,
                                              const float* __restrict__ wk,
                                              const float* __restrict__ wv,
                                              const float* __restrict__ wp) {
    int idx = blockIdx.x * 256 + threadIdx.x;
    int which = idx >> 18, off = idx & 262143;
    const float* s = (which == 0) ? wq : (which == 1) ? wk : (which == 2) ? wv : wp;
    g_w16[idx] = __float2half(s[off]);
}

// ============ prep: xT[b][t][c] fp16 ============
__global__ __launch_bounds__(256) void prep_x(const float* __restrict__ x) {
    __shared__ float tile[32][33];
    int tx = threadIdx.x, ty = threadIdx.y;
    int tBase = blockIdx.x * 32, cBase = blockIdx.y * 32, b = blockIdx.z;
    const float* X = x + (size_t)b * NC * NT;
#pragma unroll
    for (int p = 0; p < 4; p++)
        tile[ty + 8 * p][tx] = X[(size_t)(cBase + ty + 8 * p) * NT + tBase + tx];
    __syncthreads();
    __half* dst = g_xT + (size_t)b * NT * NC;
#pragma unroll
    for (int p = 0; p < 4; p++)
        dst[(size_t)(tBase + ty + 8 * p) * NC + cBase + tx] = __float2half(tile[tx][ty + 8 * p]);
}

// ============ Kernel 1: QKV fp16 ============
__global__ __launch_bounds__(256) void qkv_f16() {
    int z = blockIdx.z;
    int b = z / 3, which = z - b * 3;
    const __half* W = g_w16 + (size_t)which * NC * NC;
    const __half* X = g_xT + (size_t)b * NT * NC;

    int oBase = blockIdx.y * 128;
    int tBase = blockIdx.x * 128;

    __shared__ union {
        struct { uint32_t A[128][20]; uint32_t B[128][20]; } ab;
        unsigned short st[128][136];
    } smu;

    int tid = threadIdx.x, lane = tid & 31, wid = tid >> 5;
    int wm = wid >> 2, wn = wid & 3;
    int lr = lane >> 2, lk = lane & 3;

    float acc[4][4][4];
#pragma unroll
    for (int mi = 0; mi < 4; mi++)
#pragma unroll
        for (int nj = 0; nj < 4; nj++)
#pragma unroll
            for (int ci = 0; ci < 4; ci++) acc[mi][nj][ci] = 0.f;

    for (int k0 = 0; k0 < NC; k0 += 32) {
#pragma unroll
        for (int i = 0; i < 2; i++) {
            int idx = tid + i * 256;
            int row = idx >> 2, uu = idx & 3;
            *(uint4*)&smu.ab.A[row][uu * 4] =
                *(const uint4*)&W[(size_t)(oBase + row) * NC + k0 + uu * 8];
            *(uint4*)&smu.ab.B[row][uu * 4] =
                *(const uint4*)&X[(size_t)(tBase + row) * NC + k0 + uu * 8];
        }
        __syncthreads();
#pragma unroll
        for (int ci = 0; ci < 2; ci++) {
            int kc = ci * 8;
            uint32_t af[4][4], bf[4][2];
#pragma unroll
            for (int mi = 0; mi < 4; mi++) {
                int m0 = wm * 64 + mi * 16 + lr;
                af[mi][0] = smu.ab.A[m0][kc + lk];
                af[mi][1] = smu.ab.A[m0 + 8][kc + lk];
                af[mi][2] = smu.ab.A[m0][kc + lk + 4];
                af[mi][3] = smu.ab.A[m0 + 8][kc + lk + 4];
            }
#pragma unroll
            for (int nj = 0; nj < 4; nj++) {
                int n0 = wn * 32 + nj * 8 + lr;
                bf[nj][0] = smu.ab.B[n0][kc + lk];
                bf[nj][1] = smu.ab.B[n0][kc + lk + 4];
            }
#pragma unroll
            for (int mi = 0; mi < 4; mi++)
#pragma unroll
                for (int nj = 0; nj < 4; nj++) mma16h(acc[mi][nj], af[mi], bf[nj]);
        }
        __syncthreads();
    }

    if (which == 2) {
        __half* vh = g_vh + (size_t)b * NC * NT;
#pragma unroll
        for (int mi = 0; mi < 4; mi++) {
            int r = oBase + wm * 64 + mi * 16 + lr;
#pragma unroll
            for (int nj = 0; nj < 4; nj++) {
                int cc = tBase + wn * 32 + nj * 8 + lk * 2;
                *(__half2*)&vh[(size_t)r * NT + cc] =
                    __floats2half2_rn(acc[mi][nj][0], acc[mi][nj][1]);
                *(__half2*)&vh[(size_t)(r + 8) * NT + cc] =
                    __floats2half2_rn(acc[mi][nj][2], acc[mi][nj][3]);
            }
        }
    } else {
        __half* dst = ((which == 0) ? g_qT : g_kT) + (size_t)b * NT * NC;
#pragma unroll
        for (int mi = 0; mi < 4; mi++) {
            int r = wm * 64 + mi * 16 + lr;
#pragma unroll
            for (int nj = 0; nj < 4; nj++) {
                int cc = wn * 32 + nj * 8 + lk * 2;
                smu.st[cc][r]         = __half_as_ushort(__float2half(acc[mi][nj][0]));
                smu.st[cc + 1][r]     = __half_as_ushort(__float2half(acc[mi][nj][1]));
                smu.st[cc][r + 8]     = __half_as_ushort(__float2half(acc[mi][nj][2]));
                smu.st[cc + 1][r + 8] = __half_as_ushort(__float2half(acc[mi][nj][3]));
            }
        }
        __syncthreads();
        int row = tid >> 1, ub = (tid & 1) * 8;
#pragma unroll
        for (int j = 0; j < 8; j++) {
            *(uint4*)&dst[(size_t)(tBase + row) * NC + oBase + (ub + j) * 8] =
                *(const uint4*)&smu.st[row][(ub + j) * 8];
        }
    }
}

// ============ Kernel 2: QK^T fp16 -> fp32 raw logits ============
__global__ __launch_bounds__(256) void qk_f16() {
    int bh = blockIdx.z;
    int b = bh >> 3, h = bh & 7;
    const __half* Aq = g_qT + (size_t)b * NT * NC;
    const __half* Bk = g_kT + (size_t)b * NT * NC;
    float* out = g_attn + (size_t)bh * NT * NT;

    int qBase = blockIdx.y * 128;
    int tBase = blockIdx.x * 128;

    __shared__ uint32_t As[128][36];
    __shared__ uint32_t Bs[128][36];

    int tid = threadIdx.x, lane = tid & 31, wid = tid >> 5;
    int wm = wid >> 2, wn = wid & 3;
    int lr = lane >> 2, lk = lane & 3;

#pragma unroll
    for (int i = 0; i < 4; i++) {
        int idx = tid + i * 256;
        int row = idx >> 3, uu = idx & 7;
        *(uint4*)&As[row][uu * 4] =
            *(const uint4*)&Aq[(size_t)(qBase + row) * NC + h * 64 + uu * 8];
        *(uint4*)&Bs[row][uu * 4] =
            *(const uint4*)&Bk[(size_t)(tBase + row) * NC + h * 64 + uu * 8];
    }
    __syncthreads();

    float acc[4][4][4];
#pragma unroll
    for (int mi = 0; mi < 4; mi++)
#pragma unroll
        for (int nj = 0; nj < 4; nj++)
#pragma unroll
            for (int ci = 0; ci < 4; ci++) acc[mi][nj][ci] = 0.f;

#pragma unroll
    for (int ci = 0; ci < 4; ci++) {
        int kc = ci * 8;
        uint32_t af[4][4], bf[4][2];
#pragma unroll
        for (int mi = 0; mi < 4; mi++) {
            int m0 = wm * 64 + mi * 16 + lr;
            af[mi][0] = As[m0][kc + lk];
            af[mi][1] = As[m0 + 8][kc + lk];
            af[mi][2] = As[m0][kc + lk + 4];
            af[mi][3] = As[m0 + 8][kc + lk + 4];
        }
#pragma unroll
        for (int nj = 0; nj < 4; nj++) {
            int n0 = wn * 32 + nj * 8 + lr;
            bf[nj][0] = Bs[n0][kc + lk];
            bf[nj][1] = Bs[n0][kc + lk + 4];
        }
#pragma unroll
        for (int mi = 0; mi < 4; mi++)
#pragma unroll
            for (int nj = 0; nj < 4; nj++) mma16h(acc[mi][nj], af[mi], bf[nj]);
    }

#pragma unroll
    for (int mi = 0; mi < 4; mi++) {
        int r = qBase + wm * 64 + mi * 16 + lr;
#pragma unroll
        for (int nj = 0; nj < 4; nj++) {
            int cc = tBase + wn * 32 + nj * 8 + lk * 2;
            *(float2*)&out[(size_t)r * NT + cc] =
                make_float2(acc[mi][nj][0] * 0.125f, acc[mi][nj][1] * 0.125f);
            *(float2*)&out[(size_t)(r + 8) * NT + cc] =
                make_float2(acc[mi][nj][2] * 0.125f, acc[mi][nj][3] * 0.125f);
        }
    }
}

// ============ Kernel 3: fused mix + online softmax + AV (flash-style) ============
// Block = (b, 16 q rows). Streams T chunks of 64. Never materializes probs.
__global__ __launch_bounds__(256, 2) void msoav(const float* __restrict__ w_head) {
    extern __shared__ char smc[];
    float* whs = (float*)smc;                          // 64
    float* Ss  = whs + 64;                             // 8*16 scale factors
    __half* Ps = (__half*)(Ss + 128);                  // [8][16][72]
    __half* Vs = Ps + 8 * 16 * 72;                     // [512][72]

    int b = 3 - (int)blockIdx.y;                       // reverse for L2 reuse
    int qBase = (gridDim.x - 1 - blockIdx.x) * QB;

    int tid = threadIdx.x, lane = tid & 31, wid = tid >> 5;
    int qloc = tid >> 4, l16 = tid & 15;
    int lr = lane >> 2, lk = lane & 3;

    if (tid < 64) whs[tid] = w_head[tid];
    __syncthreads();

    float m[8], l[8], s2[8];
#pragma unroll
    for (int g = 0; g < 8; g++) { m[g] = -1e30f; l[g] = 0.f; s2[g] = 0.f; }

    float acc[8][4];   // PV accum: this warp's g, 8 n-tiles
#pragma unroll
    for (int nj = 0; nj < 8; nj++)
#pragma unroll
        for (int ci = 0; ci < 4; ci++) acc[nj][ci] = 0.f;

    const float* attnB = g_attn + (size_t)b * 8 * NT * NT + (size_t)qBase * NT;
    const __half* vB = g_vh + (size_t)b * NC * NT;

    for (int c0 = 0; c0 < NT; c0 += CH) {
        // ---- stage V chunk [512 ch][64 T] into smem ----
#pragma unroll
        for (int i = 0; i < 16; i++) {
            int idx = tid + i * 256;
            int ch = idx >> 3, seg = idx & 7;
            *(uint4*)&Vs[ch * 72 + seg * 8] =
                *(const uint4*)&vB[(size_t)ch * NT + c0 + seg * 8];
        }
        // ---- phase 1: load raw logits (8 heads), mix, online softmax ----
        float4 rv[8];
#pragma unroll
        for (int h = 0; h < 8; h++)
            rv[h] = *(const float4*)&attnB[(size_t)h * NT * NT + (size_t)qloc * NT + c0 + l16 * 4];

#pragma unroll
        for (int g = 0; g < 8; g++) {
            float mg0 = 0.f, mg1 = 0.f, mg2 = 0.f, mg3 = 0.f;
#pragma unroll
            for (int h = 0; h < 8; h++) {
                float w = whs[g * 8 + h];
                mg0 += w * rv[h].x; mg1 += w * rv[h].y;
                mg2 += w * rv[h].z; mg3 += w * rv[h].w;
            }
            float cm = fmaxf(fmaxf(mg0, mg1), fmaxf(mg2, mg3));
            cm = fmaxf(cm, __shfl_xor_sync(0xffffffffu, cm, 8));
            cm = fmaxf(cm, __shfl_xor_sync(0xffffffffu, cm, 4));
            cm = fmaxf(cm, __shfl_xor_sync(0xffffffffu, cm, 2));
            cm = fmaxf(cm, __shfl_xor_sync(0xffffffffu, cm, 1));
            float nm = fmaxf(m[g], cm);
            float sc = __expf(m[g] - nm);
            m[g] = nm;
            float e0 = __expf(mg0 - nm), e1 = __expf(mg1 - nm);
            float e2 = __expf(mg2 - nm), e3 = __expf(mg3 - nm);
            float cl = (e0 + e1) + (e2 + e3);
            float cq = (e0 * e0 + e1 * e1) + (e2 * e2 + e3 * e3);
            cl += __shfl_xor_sync(0xffffffffu, cl, 8);
            cq += __shfl_xor_sync(0xffffffffu, cq, 8);
            cl += __shfl_xor_sync(0xffffffffu, cl, 4);
            cq += __shfl_xor_sync(0xffffffffu, cq, 4);
            cl += __shfl_xor_sync(0xffffffffu, cl, 2);
            cq += __shfl_xor_sync(0xffffffffu, cq, 2);
            cl += __shfl_xor_sync(0xffffffffu, cl, 1);
            cq += __shfl_xor_sync(0xffffffffu, cq, 1);
            l[g] = l[g] * sc + cl;
            s2[g] = s2[g] * sc * sc + cq;
            if (l16 == 0) Ss[g * 16 + qloc] = sc;
            __half2 p0 = __floats2half2_rn(e0, e1);
            __half2 p1 = __floats2half2_rn(e2, e3);
            uint2 u;
            u.x = *(uint32_t*)&p0;
            u.y = *(uint32_t*)&p1;
            *(uint2*)&Ps[(g * 16 + qloc) * 72 + l16 * 4] = u;
        }
        __syncthreads();

        // ---- phase 2: warp g does P_g @ V_g^T with flash rescale ----
        {
            int g = wid;
            float sA = Ss[g * 16 + lr];
            float sB = Ss[g * 16 + lr + 8];
#pragma unroll
            for (int nj = 0; nj < 8; nj++) {
                acc[nj][0] *= sA; acc[nj][1] *= sA;
                acc[nj][2] *= sB; acc[nj][3] *= sB;
            }
            const __half* Pg = Ps + g * 16 * 72;
            const __half* Vg = Vs + g * 64 * 72;
#pragma unroll
            for (int ks = 0; ks < 4; ks++) {
                int kb = ks * 16 + lk * 2;
                uint32_t af[4];
                af[0] = *(const uint32_t*)&Pg[lr * 72 + kb];
                af[1] = *(const uint32_t*)&Pg[(lr + 8) * 72 + kb];
                af[2] = *(const uint32_t*)&Pg[lr * 72 + kb + 8];
                af[3] = *(const uint32_t*)&Pg[(lr + 8) * 72 + kb + 8];
#pragma unroll
                for (int nj = 0; nj < 8; nj++) {
                    uint32_t bf[2];
                    bf[0] = *(const uint32_t*)&Vg[(nj * 8 + lr) * 72 + kb];
                    bf[1] = *(const uint32_t*)&Vg[(nj * 8 + lr) * 72 + kb + 8];
                    mma16h(acc[nj], af, bf);
                }
            }
        }
        __syncthreads();
    }

    // ---- epilogue: write unnormalized O, l, rowsq ----
    {
        int g = wid;
        float* Op = g_oacc + ((size_t)(b * 8 + g) * NT + qBase) * NHD;
#pragma unroll
        for (int nj = 0; nj < 8; nj++) {
            int d0 = nj * 8 + lk * 2;
            *(float2*)&Op[(size_t)lr * NHD + d0] = make_float2(acc[nj][0], acc[nj][1]);
            *(float2*)&Op[(size_t)(lr + 8) * NHD + d0] = make_float2(acc[nj][2], acc[nj][3]);
        }
    }
    if (l16 == 0) {
#pragma unroll
        for (int g = 0; g < 8; g++) {
            int r = (b * 8 + g) * NT + qBase + qloc;
            g_l[r] = l[g];
            g_rowsq[r] = s2[g] / (l[g] * l[g]);
        }
    }
}

// ============ Kernel 4: vsum from fp16 v ============
__global__ __launch_bounds__(256) void vsum_f16() {
    __shared__ float sbuf[8];
    int row = blockIdx.x;
    const __half2* p = (const __half2*)(g_vh + (size_t)row * NT) + threadIdx.x * 2;
    float2 a = __half22float2(p[0]);
    float2 bb = __half22float2(p[1]);
    float s = (a.x + a.y) + (bb.x + bb.y);
    int lane = threadIdx.x & 31, w = threadIdx.x >> 5;
#pragma unroll
    for (int o = 16; o > 0; o >>= 1) s += __shfl_xor_sync(0xffffffffu, s, o);
    if (lane == 0) sbuf[w] = s;
    __syncthreads();
    if (threadIdx.x == 0) {
        float tt = 0.f;
        for (int i = 0; i < 8; i++) tt += sbuf[i];
        g_vsum[row] = tt;
    }
}

// ============ Kernel 5: finalize InstanceNorm params ============
__global__ __launch_bounds__(256) void finalize_kernel(const float* __restrict__ gamma,
                                                       const float* __restrict__ beta) {
    __shared__ float sbuf[8];
    int grp = blockIdx.x;
    float s = 0.f;
    for (int i = threadIdx.x; i < NT; i += 256) s += g_rowsq[grp * NT + i];
    int lane = threadIdx.x & 31, w = threadIdx.x >> 5;
#pragma unroll
    for (int o = 16; o > 0; o >>= 1) s += __shfl_xor_sync(0xffffffffu, s, o);
    if (lane == 0) sbuf[w] = s;
    __syncthreads();
    if (threadIdx.x == 0) {
        float sumsq = 0.f;
        for (int i = 0; i < 8; i++) sumsq += sbuf[i];
        const float invN = 1.f / (1024.f * 1024.f);
        float mean = 1.f / 1024.f;
        float var = sumsq * invN - mean * mean;
        int h = grp & 7;
        float alpha = gamma[h] * rsqrtf(var + EPS_IN);
        g_alpha[grp] = alpha;
        g_betac[grp] = beta[h] - alpha * mean;
    }
}

// ============ Kernel 6: normalize O + InstanceNorm fold -> fp16 mid ============
__global__ __launch_bounds__(256) void o_epilogue() {
    int bh = blockIdx.y;
    int qt = blockIdx.x;   // 16 tiles of 64 q
    float alpha = g_alpha[bh], bc = g_betac[bh];
    size_t base = (size_t)bh * NT * NHD + (size_t)qt * 64 * NHD;
#pragma unroll
    for (int i = 0; i < 4; i++) {
        int e4 = threadIdx.x + i * 256;    // 1024 float4 groups
        int q = qt * 64 + (e4 >> 4);
        int d = (e4 & 15) * 4;
        float4 o = *(const float4*)&g_oacc[base + (size_t)(e4 >> 4) * NHD + d];
        float invl = 1.f / g_l[bh * NT + q];
        float4 vs = *(const float4*)&g_vsum[bh * NHD + d];
        __half2 h0 = __floats2half2_rn(alpha * o.x * invl + bc * vs.x,
                                       alpha * o.y * invl + bc * vs.y);
        __half2 h1 = __floats2half2_rn(alpha * o.z * invl + bc * vs.z,
                                       alpha * o.w * invl + bc * vs.w);
        uint2 u;
        u.x = *(uint32_t*)&h0;
        u.y = *(uint32_t*)&h1;
        *(uint2*)&g_outh[base + (size_t)(e4 >> 4) * NHD + d] = u;
    }
}

// ============ Kernel 7: projection fp16 ============
__global__ __launch_bounds__(256) void proj_f16(const float* __restrict__ b_proj,
                                                float* __restrict__ outF) {
    int b = blockIdx.z;
    int coBase = blockIdx.y * 128;
    int tBase = blockIdx.x * 128;
    const __half* W = g_w16 + (size_t)3 * NC * NC;
    const __half* M = g_outh + (size_t)b * NT * NC;

    __shared__ uint32_t As[128][20];
    __shared__ uint32_t Bs[128][20];

    int tid = threadIdx.x, lane = tid & 31, wid = tid >> 5;
    int wm = wid >> 2, wn = wid & 3;
    int lr = lane >> 2, lk = lane & 3;

    float acc[4][4][4];
#pragma unroll
    for (int mi = 0; mi < 4; mi++)
#pragma unroll
        for (int nj = 0; nj < 4; nj++)
#pragma unroll
            for (int ci = 0; ci < 4; ci++) acc[mi][nj][ci] = 0.f;

    for (int k0 = 0; k0 < NC; k0 += 32) {
#pragma unroll
        for (int i = 0; i < 2; i++) {
            int idx = tid + i * 256;
            int row = idx >> 2, uu = idx & 3;
            *(uint4*)&As[row][uu * 4] =
                *(const uint4*)&W[(size_t)(coBase + row) * NC + k0 + uu * 8];
            *(uint4*)&Bs[row][uu * 4] =
                *(const uint4*)&M[(size_t)(tBase + row) * NC + k0 + uu * 8];
        }
        __syncthreads();
#pragma unroll
        for (int ci = 0; ci < 2; ci++) {
            int kc = ci * 8;
            uint32_t af[4][4], bf[4][2];
#pragma unroll
            for (int mi = 0; mi < 4; mi++) {
                int m0 = wm * 64 + mi * 16 + lr;
                af[mi][0] = As[m0][kc + lk];
                af[mi][1] = As[m0 + 8][kc + lk];
                af[mi][2] = As[m0][kc + lk + 4];
                af[mi][3] = As[m0 + 8][kc + lk + 4];
            }
#pragma unroll
            for (int nj = 0; nj < 4; nj++) {
                int n0 = wn * 32 + nj * 8 + lr;
                bf[nj][0] = Bs[n0][kc + lk];
                bf[nj][1] = Bs[n0][kc + lk + 4];
            }
#pragma unroll
            for (int mi = 0; mi < 4; mi++)
#pragma unroll
                for (int nj = 0; nj < 4; nj++) mma16h(acc[mi][nj], af[mi], bf[nj]);
        }
        __syncthreads();
    }
#pragma unroll
    for (int mi = 0; mi < 4; mi++) {
        int co = coBase + wm * 64 + mi * 16 + lr;
        float bias0 = b_proj[co], bias1 = b_proj[co + 8];
        float* op0 = outF + (size_t)b * NC * NT + (size_t)co * NT;
        float* op1 = op0 + (size_t)8 * NT;
#pragma unroll
        for (int nj = 0; nj < 4; nj++) {
            int cc = tBase + wn * 32 + nj * 8 + lk * 2;
            *(float2*)&op0[cc] = make_float2(acc[mi][nj][0] + bias0, acc[mi][nj][1] + bias0);
            *(float2*)&op1[cc] = make_float2(acc[mi][nj][2] + bias1, acc[mi][nj][3] + bias1);
        }
    }
}

// ---------------- launch ----------------
extern "C" void kernel_launch(void* const* d_in, const int* in_sizes, int n_in,
                              void* d_out, int out_size) {
    (void)in_sizes; (void)n_in; (void)out_size;
    const float* x        = (const float*)d_in[0];
    const float* w_q      = (const float*)d_in[1];
    const float* w_k      = (const float*)d_in[2];
    const float* w_v      = (const float*)d_in[3];
    const float* w_head   = (const float*)d_in[4];
    const float* in_gamma = (const float*)d_in[5];
    const float* in_beta  = (const float*)d_in[6];
    const float* w_proj   = (const float*)d_in[7];
    const float* b_proj   = (const float*)d_in[8];
    float* outF = (float*)d_out;

    const int MSOAV_SMEM = (64 + 128) * 4 + (8 * 16 * 72 + 512 * 72) * 2;  // 92928
    cudaFuncSetAttribute(msoav, cudaFuncAttributeMaxDynamicSharedMemorySize, MSOAV_SMEM);

    prep_w<<<4096, 256>>>(w_q, w_k, w_v, w_proj);
    prep_x<<<dim3(32, 16, 4), dim3(32, 8)>>>(x);
    qkv_f16<<<dim3(8, 4, 12), 256>>>();
    qk_f16<<<dim3(8, 8, 32), 256>>>();
    vsum_f16<<<2048, 256>>>();
    msoav<<<dim3(64, 4), 256, MSOAV_SMEM>>>(w_head);
    finalize_kernel<<<32, 256>>>(in_gamma, in_beta);
    o_epilogue<<<dim3(16, 32), 256>>>();
    proj_f16<<<dim3(8, 4, 4), 256>>>(b_proj, outF);
}

// round 10
// speedup vs baseline: 1.1278x; 1.1260x over previous
#include <cuda_runtime.h>
#include <cuda_fp16.h>
#include <math.h>
#include <stdint.h>

#define NB 4
#define NC 512
#define NT 1024
#define NHEADS 8
#define NHD 64
#define EPS_IN 1e-5f
#define QT 32
#define CH 64

// ---------------- device scratch ----------------
__device__ __half g_w16[4 * NC * NC];                      // wq,wk,wv,wproj fp16
__device__ __half g_xT[NB * NT * NC];                      // x transposed [b][t][c]
__device__ __half g_qT[NB * NT * NC];
__device__ __half g_kT[NB * NT * NC];
__device__ __half g_vh[NB * NC * NT];                      // v [b][c][t]
__device__ float g_oacc[NB * NHEADS * NT * NHD];           // unnormalized PV accum
__device__ float g_l[NB * NHEADS * NT];                    // softmax denominators
__device__ __half g_outh[NB * NHEADS * NT * NHD];          // mid, flat == [b][t][c]
__device__ float g_vsum[NB * NC];
__device__ float g_rowsq[NB * NHEADS * NT];
__device__ float g_alpha[32];
__device__ float g_betac[32];

__device__ __forceinline__ void mma16h(float* c, const uint32_t* a, const uint32_t* b) {
    asm volatile("mma.sync.aligned.m16n8k16.row.col.f32.f16.f16.f32 "
        "{%0,%1,%2,%3}, {%4,%5,%6,%7}, {%8,%9}, {%0,%1,%2,%3};\n"
        : "+f"(c[0]), "+f"(c[1]), "+f"(c[2]), "+f"(c[3])
        : "r"(a[0]), "r"(a[1]), "r"(a[2]), "r"(a[3]), "r"(b[0]), "r"(b[1]));
}
__device__ __forceinline__ float ex2f(float x) {
    float r;
    asm("ex2.approx.ftz.f32 %0, %1;" : "=f"(r) : "f"(x));
    return r;
}

// ============ prep: weights -> fp16 ============
__global__ __launch_bounds__(256) void prep_w(const float* __restrict__ wq,
                                              const float* __restrict__ wk,
                                              const float* __restrict__ wv,
                                              const float* __restrict__ wp) {
    int idx = blockIdx.x * 256 + threadIdx.x;
    int which = idx >> 18, off = idx & 262143;
    const float* s = (which == 0) ? wq : (which == 1) ? wk : (which == 2) ? wv : wp;
    g_w16[idx] = __float2half(s[off]);
}

// ============ prep: xT[b][t][c] fp16 ============
__global__ __launch_bounds__(256) void prep_x(const float* __restrict__ x) {
    __shared__ float tile[32][33];
    int tx = threadIdx.x, ty = threadIdx.y;
    int tBase = blockIdx.x * 32, cBase = blockIdx.y * 32, b = blockIdx.z;
    const float* X = x + (size_t)b * NC * NT;
#pragma unroll
    for (int p = 0; p < 4; p++)
        tile[ty + 8 * p][tx] = X[(size_t)(cBase + ty + 8 * p) * NT + tBase + tx];
    __syncthreads();
    __half* dst = g_xT + (size_t)b * NT * NC;
#pragma unroll
    for (int p = 0; p < 4; p++)
        dst[(size_t)(tBase + ty + 8 * p) * NC + cBase + tx] = __float2half(tile[tx][ty + 8 * p]);
}

// ============ Kernel 1: QKV fp16 ============
__global__ __launch_bounds__(256) void qkv_f16() {
    int z = blockIdx.z;
    int b = z / 3, which = z - b * 3;
    const __half* W = g_w16 + (size_t)which * NC * NC;
    const __half* X = g_xT + (size_t)b * NT * NC;

    int oBase = blockIdx.y * 128;
    int tBase = blockIdx.x * 128;

    __shared__ union {
        struct { uint32_t A[128][20]; uint32_t B[128][20]; } ab;
        unsigned short st[128][136];
    } smu;

    int tid = threadIdx.x, lane = tid & 31, wid = tid >> 5;
    int wm = wid >> 2, wn = wid & 3;
    int lr = lane >> 2, lk = lane & 3;

    float acc[4][4][4];
#pragma unroll
    for (int mi = 0; mi < 4; mi++)
#pragma unroll
        for (int nj = 0; nj < 4; nj++)
#pragma unroll
            for (int ci = 0; ci < 4; ci++) acc[mi][nj][ci] = 0.f;

    for (int k0 = 0; k0 < NC; k0 += 32) {
#pragma unroll
        for (int i = 0; i < 2; i++) {
            int idx = tid + i * 256;
            int row = idx >> 2, uu = idx & 3;
            *(uint4*)&smu.ab.A[row][uu * 4] =
                *(const uint4*)&W[(size_t)(oBase + row) * NC + k0 + uu * 8];
            *(uint4*)&smu.ab.B[row][uu * 4] =
                *(const uint4*)&X[(size_t)(tBase + row) * NC + k0 + uu * 8];
        }
        __syncthreads();
#pragma unroll
        for (int ci = 0; ci < 2; ci++) {
            int kc = ci * 8;
            uint32_t af[4][4], bf[4][2];
#pragma unroll
            for (int mi = 0; mi < 4; mi++) {
                int m0 = wm * 64 + mi * 16 + lr;
                af[mi][0] = smu.ab.A[m0][kc + lk];
                af[mi][1] = smu.ab.A[m0 + 8][kc + lk];
                af[mi][2] = smu.ab.A[m0][kc + lk + 4];
                af[mi][3] = smu.ab.A[m0 + 8][kc + lk + 4];
            }
#pragma unroll
            for (int nj = 0; nj < 4; nj++) {
                int n0 = wn * 32 + nj * 8 + lr;
                bf[nj][0] = smu.ab.B[n0][kc + lk];
                bf[nj][1] = smu.ab.B[n0][kc + lk + 4];
            }
#pragma unroll
            for (int mi = 0; mi < 4; mi++)
#pragma unroll
                for (int nj = 0; nj < 4; nj++) mma16h(acc[mi][nj], af[mi], bf[nj]);
        }
        __syncthreads();
    }

    if (which == 2) {
        __half* vh = g_vh + (size_t)b * NC * NT;
#pragma unroll
        for (int mi = 0; mi < 4; mi++) {
            int r = oBase + wm * 64 + mi * 16 + lr;
#pragma unroll
            for (int nj = 0; nj < 4; nj++) {
                int cc = tBase + wn * 32 + nj * 8 + lk * 2;
                *(__half2*)&vh[(size_t)r * NT + cc] =
                    __floats2half2_rn(acc[mi][nj][0], acc[mi][nj][1]);
                *(__half2*)&vh[(size_t)(r + 8) * NT + cc] =
                    __floats2half2_rn(acc[mi][nj][2], acc[mi][nj][3]);
            }
        }
    } else {
        __half* dst = ((which == 0) ? g_qT : g_kT) + (size_t)b * NT * NC;
#pragma unroll
        for (int mi = 0; mi < 4; mi++) {
            int r = wm * 64 + mi * 16 + lr;
#pragma unroll
            for (int nj = 0; nj < 4; nj++) {
                int cc = wn * 32 + nj * 8 + lk * 2;
                smu.st[cc][r]         = __half_as_ushort(__float2half(acc[mi][nj][0]));
                smu.st[cc + 1][r]     = __half_as_ushort(__float2half(acc[mi][nj][1]));
                smu.st[cc][r + 8]     = __half_as_ushort(__float2half(acc[mi][nj][2]));
                smu.st[cc + 1][r + 8] = __half_as_ushort(__float2half(acc[mi][nj][3]));
            }
        }
        __syncthreads();
        int row = tid >> 1, ub = (tid & 1) * 8;
#pragma unroll
        for (int j = 0; j < 8; j++) {
            *(uint4*)&dst[(size_t)(tBase + row) * NC + oBase + (ub + j) * 8] =
                *(const uint4*)&smu.st[row][(ub + j) * 8];
        }
    }
}

// ============ Kernel 2: fully fused QK -> mix -> softmax -> PV ============
// Block = (b, 32 q rows), 8 warps. g_attn never materialized.
__global__ __launch_bounds__(256) void fa(const float* __restrict__ w_head) {
    extern __shared__ char smc[];
    __half* QsH = (__half*)smc;                        // 8h x 32q x 72d   (36864 B)
    __half* KVH = (__half*)(smc + 36864);              // K: 8h x 64t x 72d / V: 512c x 72t (73728 B)
    float*  SsF = (float*)(smc + 110592);              // 8h x 32q x 68t   (69632 B)
    __half* PsH = (__half*)(smc + 180224);             // 8g x 32q x 72t   (36864 B)
    float*  Scs = (float*)(smc + 217088);              // 8g x 32q         (1024 B)
    float*  whs = (float*)(smc + 218112);              // 64               (256 B)
    uint32_t* QsU = (uint32_t*)QsH;
    uint32_t* KVU = (uint32_t*)KVH;
    uint32_t* PsU = (uint32_t*)PsH;

    int b = blockIdx.y;
    int qBase = blockIdx.x * QT;
    int tid = threadIdx.x, lane = tid & 31, wid = tid >> 5;
    int lr = lane >> 2, lk = lane & 3;
    int qD = tid >> 3, s8 = (tid & 7) * 8;   // D-phase mapping

    if (tid < 64) whs[tid] = w_head[tid] * 1.4426950408889634f;   // fold log2(e)

    // stage Q tile (pre-scaled by 0.125, exact in fp16)
    {
        const __half* Qsrc = g_qT + ((size_t)b * NT + qBase) * NC;
        __half2 sc8 = __float2half2_rn(0.125f);
#pragma unroll
        for (int i = 0; i < 8; i++) {
            int idx = tid + i * 256;
            int q = idx >> 6, u = idx & 63;
            uint4 v = *(const uint4*)&Qsrc[q * NC + u * 8];
            __half2* pv2 = (__half2*)&v;
            pv2[0] = __hmul2(pv2[0], sc8); pv2[1] = __hmul2(pv2[1], sc8);
            pv2[2] = __hmul2(pv2[2], sc8); pv2[3] = __hmul2(pv2[3], sc8);
            *(uint4*)&QsH[(u >> 3) * 2304 + q * 72 + (u & 7) * 8] = v;
        }
    }

    float m[8], l[8], s2[8];
#pragma unroll
    for (int g = 0; g < 8; g++) { m[g] = -1e30f; l[g] = 0.f; s2[g] = 0.f; }

    float pv[2][8][4];
#pragma unroll
    for (int mi = 0; mi < 2; mi++)
#pragma unroll
        for (int nj = 0; nj < 8; nj++)
#pragma unroll
            for (int ci = 0; ci < 4; ci++) pv[mi][nj][ci] = 0.f;

    const __half* Ksrc = g_kT + (size_t)b * NT * NC;
    const __half* Vsrc = g_vh + (size_t)b * NC * NT;

    __syncthreads();

    for (int c0 = 0; c0 < NT; c0 += CH) {
        // ---- A: stage K chunk [8h][64t][72d] ----
#pragma unroll
        for (int i = 0; i < 16; i++) {
            int idx = tid + i * 256;
            int t = idx >> 6, u = idx & 63;
            uint4 v = *(const uint4*)&Ksrc[(size_t)(c0 + t) * NC + u * 8];
            *(uint4*)&KVH[(u >> 3) * 4608 + t * 72 + (u & 7) * 8] = v;
        }
        __syncthreads();

        // ---- B+C: warp h computes S_h (32q x 64T), stores fp32 to smem ----
        {
            int h = wid;
            float sacc[2][8][4];
#pragma unroll
            for (int mi = 0; mi < 2; mi++)
#pragma unroll
                for (int nj = 0; nj < 8; nj++)
#pragma unroll
                    for (int ci = 0; ci < 4; ci++) sacc[mi][nj][ci] = 0.f;
#pragma unroll
            for (int ks = 0; ks < 4; ks++) {
                int kb = ks * 8;
                uint32_t af[2][4], bf[8][2];
#pragma unroll
                for (int mi = 0; mi < 2; mi++) {
                    int m0 = mi * 16 + lr;
                    af[mi][0] = QsU[h * 1152 + m0 * 36 + kb + lk];
                    af[mi][1] = QsU[h * 1152 + (m0 + 8) * 36 + kb + lk];
                    af[mi][2] = QsU[h * 1152 + m0 * 36 + kb + lk + 4];
                    af[mi][3] = QsU[h * 1152 + (m0 + 8) * 36 + kb + lk + 4];
                }
#pragma unroll
                for (int nj = 0; nj < 8; nj++) {
                    int n0 = nj * 8 + lr;
                    bf[nj][0] = KVU[h * 2304 + n0 * 36 + kb + lk];
                    bf[nj][1] = KVU[h * 2304 + n0 * 36 + kb + lk + 4];
                }
#pragma unroll
                for (int mi = 0; mi < 2; mi++)
#pragma unroll
                    for (int nj = 0; nj < 8; nj++) mma16h(sacc[mi][nj], af[mi], bf[nj]);
            }
            float* Sh = SsF + wid * 2176;
#pragma unroll
            for (int mi = 0; mi < 2; mi++) {
                int r0 = mi * 16 + lr;
#pragma unroll
                for (int nj = 0; nj < 8; nj++) {
                    int cc = nj * 8 + lk * 2;
                    *(float2*)&Sh[r0 * 68 + cc] = make_float2(sacc[mi][nj][0], sacc[mi][nj][1]);
                    *(float2*)&Sh[(r0 + 8) * 68 + cc] = make_float2(sacc[mi][nj][2], sacc[mi][nj][3]);
                }
            }
        }
        __syncthreads();

        // ---- D: mix (f32x2) + base-2 online softmax + P fp16 ----
        {
            unsigned long long xh[8][4];
            const float* Sq = SsF + qD * 68 + s8;
#pragma unroll
            for (int h = 0; h < 8; h++) {
                const double2* dp = (const double2*)(Sq + h * 2176);
                double2 d0 = dp[0], d1 = dp[1];
                xh[h][0] = __double_as_longlong(d0.x);
                xh[h][1] = __double_as_longlong(d0.y);
                xh[h][2] = __double_as_longlong(d1.x);
                xh[h][3] = __double_as_longlong(d1.y);
            }
#pragma unroll
            for (int g = 0; g < 8; g++) {
                unsigned long long a0 = 0, a1 = 0, a2 = 0, a3 = 0;
#pragma unroll
                for (int h = 0; h < 8; h++) {
                    float w = whs[g * 8 + h];
                    unsigned long long w2;
                    asm("mov.b64 %0, {%1, %1};" : "=l"(w2) : "f"(w));
                    asm("fma.rn.f32x2 %0, %1, %2, %0;" : "+l"(a0) : "l"(w2), "l"(xh[h][0]));
                    asm("fma.rn.f32x2 %0, %1, %2, %0;" : "+l"(a1) : "l"(w2), "l"(xh[h][1]));
                    asm("fma.rn.f32x2 %0, %1, %2, %0;" : "+l"(a2) : "l"(w2), "l"(xh[h][2]));
                    asm("fma.rn.f32x2 %0, %1, %2, %0;" : "+l"(a3) : "l"(w2), "l"(xh[h][3]));
                }
                float mg[8];
                asm("mov.b64 {%0, %1}, %2;" : "=f"(mg[0]), "=f"(mg[1]) : "l"(a0));
                asm("mov.b64 {%0, %1}, %2;" : "=f"(mg[2]), "=f"(mg[3]) : "l"(a1));
                asm("mov.b64 {%0, %1}, %2;" : "=f"(mg[4]), "=f"(mg[5]) : "l"(a2));
                asm("mov.b64 {%0, %1}, %2;" : "=f"(mg[6]), "=f"(mg[7]) : "l"(a3));

                float cm = fmaxf(fmaxf(fmaxf(mg[0], mg[1]), fmaxf(mg[2], mg[3])),
                                 fmaxf(fmaxf(mg[4], mg[5]), fmaxf(mg[6], mg[7])));
                cm = fmaxf(cm, __shfl_xor_sync(0xffffffffu, cm, 1));
                cm = fmaxf(cm, __shfl_xor_sync(0xffffffffu, cm, 2));
                cm = fmaxf(cm, __shfl_xor_sync(0xffffffffu, cm, 4));
                float nm = fmaxf(m[g], cm);
                float sc = ex2f(m[g] - nm);
                m[g] = nm;
                float e0 = ex2f(mg[0] - nm), e1 = ex2f(mg[1] - nm);
                float e2 = ex2f(mg[2] - nm), e3 = ex2f(mg[3] - nm);
                float e4 = ex2f(mg[4] - nm), e5 = ex2f(mg[5] - nm);
                float e6 = ex2f(mg[6] - nm), e7 = ex2f(mg[7] - nm);
                float cl = ((e0 + e1) + (e2 + e3)) + ((e4 + e5) + (e6 + e7));
                float cq = ((e0 * e0 + e1 * e1) + (e2 * e2 + e3 * e3)) +
                           ((e4 * e4 + e5 * e5) + (e6 * e6 + e7 * e7));
                l[g] = l[g] * sc + cl;
                s2[g] = s2[g] * (sc * sc) + cq;
                __half2 p0 = __floats2half2_rn(e0, e1);
                __half2 p1 = __floats2half2_rn(e2, e3);
                __half2 p2 = __floats2half2_rn(e4, e5);
                __half2 p3 = __floats2half2_rn(e6, e7);
                uint4 u;
                u.x = *(uint32_t*)&p0; u.y = *(uint32_t*)&p1;
                u.z = *(uint32_t*)&p2; u.w = *(uint32_t*)&p3;
                *(uint4*)&PsH[g * 2304 + qD * 72 + s8] = u;
                if ((tid & 7) == 0) Scs[g * 32 + qD] = sc;
            }
        }
        // ---- E: stage V chunk [512c][72t] (K region now dead) ----
#pragma unroll
        for (int i = 0; i < 16; i++) {
            int idx = tid + i * 256;
            int c = idx >> 3, seg = idx & 7;
            uint4 v = *(const uint4*)&Vsrc[(size_t)c * NT + c0 + seg * 8];
            *(uint4*)&KVH[c * 72 + seg * 8] = v;
        }
        __syncthreads();

        // ---- F: warp g accumulates P_g @ V_g^T with rescale ----
        {
            int g = wid;
            float s00 = Scs[g * 32 + lr],      s01 = Scs[g * 32 + lr + 8];
            float s10 = Scs[g * 32 + 16 + lr], s11 = Scs[g * 32 + 24 + lr];
#pragma unroll
            for (int nj = 0; nj < 8; nj++) {
                pv[0][nj][0] *= s00; pv[0][nj][1] *= s00;
                pv[0][nj][2] *= s01; pv[0][nj][3] *= s01;
                pv[1][nj][0] *= s10; pv[1][nj][1] *= s10;
                pv[1][nj][2] *= s11; pv[1][nj][3] *= s11;
            }
#pragma unroll
            for (int ks = 0; ks < 4; ks++) {
                int kb = ks * 8;
                uint32_t af[2][4], bf[8][2];
#pragma unroll
                for (int mi = 0; mi < 2; mi++) {
                    int m0 = mi * 16 + lr;
                    af[mi][0] = PsU[g * 1152 + m0 * 36 + kb + lk];
                    af[mi][1] = PsU[g * 1152 + (m0 + 8) * 36 + kb + lk];
                    af[mi][2] = PsU[g * 1152 + m0 * 36 + kb + lk + 4];
                    af[mi][3] = PsU[g * 1152 + (m0 + 8) * 36 + kb + lk + 4];
                }
#pragma unroll
                for (int nj = 0; nj < 8; nj++) {
                    int n0 = g * 64 + nj * 8 + lr;
                    bf[nj][0] = KVU[n0 * 36 + kb + lk];
                    bf[nj][1] = KVU[n0 * 36 + kb + lk + 4];
                }
#pragma unroll
                for (int mi = 0; mi < 2; mi++)
#pragma unroll
                    for (int nj = 0; nj < 8; nj++) mma16h(pv[mi][nj], af[mi], bf[nj]);
            }
        }
        __syncthreads();
    }

    // ---- epilogue: reduce l/s2 per row, write O/l/rowsq ----
#pragma unroll
    for (int g = 0; g < 8; g++) {
        float lv = l[g], sv = s2[g];
        lv += __shfl_xor_sync(0xffffffffu, lv, 1);
        sv += __shfl_xor_sync(0xffffffffu, sv, 1);
        lv += __shfl_xor_sync(0xffffffffu, lv, 2);
        sv += __shfl_xor_sync(0xffffffffu, sv, 2);
        lv += __shfl_xor_sync(0xffffffffu, lv, 4);
        sv += __shfl_xor_sync(0xffffffffu, sv, 4);
        if ((tid & 7) == 0) {
            int r = (b * 8 + g) * NT + qBase + qD;
            g_l[r] = lv;
            g_rowsq[r] = sv / (lv * lv);
        }
    }
    {
        int g = wid;
        float* Op = g_oacc + ((size_t)(b * 8 + g) * NT + qBase) * NHD;
#pragma unroll
        for (int mi = 0; mi < 2; mi++) {
            int r0 = mi * 16 + lr;
#pragma unroll
            for (int nj = 0; nj < 8; nj++) {
                int cc = nj * 8 + lk * 2;
                *(float2*)&Op[(size_t)r0 * NHD + cc] = make_float2(pv[mi][nj][0], pv[mi][nj][1]);
                *(float2*)&Op[(size_t)(r0 + 8) * NHD + cc] = make_float2(pv[mi][nj][2], pv[mi][nj][3]);
            }
        }
    }
}

// ============ Kernel 4: vsum from fp16 v ============
__global__ __launch_bounds__(256) void vsum_f16() {
    __shared__ float sbuf[8];
    int row = blockIdx.x;
    const __half2* p = (const __half2*)(g_vh + (size_t)row * NT) + threadIdx.x * 2;
    float2 a = __half22float2(p[0]);
    float2 bb = __half22float2(p[1]);
    float s = (a.x + a.y) + (bb.x + bb.y);
    int lane = threadIdx.x & 31, w = threadIdx.x >> 5;
#pragma unroll
    for (int o = 16; o > 0; o >>= 1) s += __shfl_xor_sync(0xffffffffu, s, o);
    if (lane == 0) sbuf[w] = s;
    __syncthreads();
    if (threadIdx.x == 0) {
        float tt = 0.f;
        for (int i = 0; i < 8; i++) tt += sbuf[i];
        g_vsum[row] = tt;
    }
}

// ============ Kernel 5: finalize InstanceNorm params ============
__global__ __launch_bounds__(256) void finalize_kernel(const float* __restrict__ gamma,
                                                       const float* __restrict__ beta) {
    __shared__ float sbuf[8];
    int grp = blockIdx.x;
    float s = 0.f;
    for (int i = threadIdx.x; i < NT; i += 256) s += g_rowsq[grp * NT + i];
    int lane = threadIdx.x & 31, w = threadIdx.x >> 5;
#pragma unroll
    for (int o = 16; o > 0; o >>= 1) s += __shfl_xor_sync(0xffffffffu, s, o);
    if (lane == 0) sbuf[w] = s;
    __syncthreads();
    if (threadIdx.x == 0) {
        float sumsq = 0.f;
        for (int i = 0; i < 8; i++) sumsq += sbuf[i];
        const float invN = 1.f / (1024.f * 1024.f);
        float mean = 1.f / 1024.f;
        float var = sumsq * invN - mean * mean;
        int h = grp & 7;
        float alpha = gamma[h] * rsqrtf(var + EPS_IN);
        g_alpha[grp] = alpha;
        g_betac[grp] = beta[h] - alpha * mean;
    }
}

// ============ Kernel 6: normalize O + InstanceNorm fold -> fp16 mid ============
__global__ __launch_bounds__(256) void o_epilogue() {
    int bh = blockIdx.y;
    int qt = blockIdx.x;
    float alpha = g_alpha[bh], bc = g_betac[bh];
    size_t base = (size_t)bh * NT * NHD + (size_t)qt * 64 * NHD;
#pragma unroll
    for (int i = 0; i < 4; i++) {
        int e4 = threadIdx.x + i * 256;
        int q = qt * 64 + (e4 >> 4);
        int d = (e4 & 15) * 4;
        float4 o = *(const float4*)&g_oacc[base + (size_t)(e4 >> 4) * NHD + d];
        float invl = 1.f / g_l[bh * NT + q];
        float4 vs = *(const float4*)&g_vsum[bh * NHD + d];
        __half2 h0 = __floats2half2_rn(alpha * o.x * invl + bc * vs.x,
                                       alpha * o.y * invl + bc * vs.y);
        __half2 h1 = __floats2half2_rn(alpha * o.z * invl + bc * vs.z,
                                       alpha * o.w * invl + bc * vs.w);
        uint2 u;
        u.x = *(uint32_t*)&h0;
        u.y = *(uint32_t*)&h1;
        *(uint2*)&g_outh[base + (size_t)(e4 >> 4) * NHD + d] = u;
    }
}

// ============ Kernel 7: projection fp16 ============
__global__ __launch_bounds__(256) void proj_f16(const float* __restrict__ b_proj,
                                                float* __restrict__ outF) {
    int b = blockIdx.z;
    int coBase = blockIdx.y * 128;
    int tBase = blockIdx.x * 128;
    const __half* W = g_w16 + (size_t)3 * NC * NC;
    const __half* M = g_outh + (size_t)b * NT * NC;

    __shared__ uint32_t As[128][20];
    __shared__ uint32_t Bs[128][20];

    int tid = threadIdx.x, lane = tid & 31, wid = tid >> 5;
    int wm = wid >> 2, wn = wid & 3;
    int lr = lane >> 2, lk = lane & 3;

    float acc[4][4][4];
#pragma unroll
    for (int mi = 0; mi < 4; mi++)
#pragma unroll
        for (int nj = 0; nj < 4; nj++)
#pragma unroll
            for (int ci = 0; ci < 4; ci++) acc[mi][nj][ci] = 0.f;

    for (int k0 = 0; k0 < NC; k0 += 32) {
#pragma unroll
        for (int i = 0; i < 2; i++) {
            int idx = tid + i * 256;
            int row = idx >> 2, uu = idx & 3;
            *(uint4*)&As[row][uu * 4] =
                *(const uint4*)&W[(size_t)(coBase + row) * NC + k0 + uu * 8];
            *(uint4*)&Bs[row][uu * 4] =
                *(const uint4*)&M[(size_t)(tBase + row) * NC + k0 + uu * 8];
        }
        __syncthreads();
#pragma unroll
        for (int ci = 0; ci < 2; ci++) {
            int kc = ci * 8;
            uint32_t af[4][4], bf[4][2];
#pragma unroll
            for (int mi = 0; mi < 4; mi++) {
                int m0 = wm * 64 + mi * 16 + lr;
                af[mi][0] = As[m0][kc + lk];
                af[mi][1] = As[m0 + 8][kc + lk];
                af[mi][2] = As[m0][kc + lk + 4];
                af[mi][3] = As[m0 + 8][kc + lk + 4];
            }
#pragma unroll
            for (int nj = 0; nj < 4; nj++) {
                int n0 = wn * 32 + nj * 8 + lr;
                bf[nj][0] = Bs[n0][kc + lk];
                bf[nj][1] = Bs[n0][kc + lk + 4];
            }
#pragma unroll
            for (int mi = 0; mi < 4; mi++)
#pragma unroll
                for (int nj = 0; nj < 4; nj++) mma16h(acc[mi][nj], af[mi], bf[nj]);
        }
        __syncthreads();
    }
#pragma unroll
    for (int mi = 0; mi < 4; mi++) {
        int co = coBase + wm * 64 + mi * 16 + lr;
        float bias0 = b_proj[co], bias1 = b_proj[co + 8];
        float* op0 = outF + (size_t)b * NC * NT + (size_t)co * NT;
        float* op1 = op0 + (size_t)8 * NT;
#pragma unroll
        for (int nj = 0; nj < 4; nj++) {
            int cc = tBase + wn * 32 + nj * 8 + lk * 2;
            *(float2*)&op0[cc] = make_float2(acc[mi][nj][0] + bias0, acc[mi][nj][1] + bias0);
            *(float2*)&op1[cc] = make_float2(acc[mi][nj][2] + bias1, acc[mi][nj][3] + bias1);
        }
    }
}

// ---------------- launch ----------------
extern "C" void kernel_launch(void* const* d_in, const int* in_sizes, int n_in,
                              void* d_out, int out_size) {
    (void)in_sizes; (void)n_in; (void)out_size;
    const float* x        = (const float*)d_in[0];
    const float* w_q      = (const float*)d_in[1];
    const float* w_k      = (const float*)d_in[2];
    const float* w_v      = (const float*)d_in[3];
    const float* w_head   = (const float*)d_in[4];
    const float* in_gamma = (const float*)d_in[5];
    const float* in_beta  = (const float*)d_in[6];
    const float* w_proj   = (const float*)d_in[7];
    const float* b_proj   = (const float*)d_in[8];
    float* outF = (float*)d_out;

    const int FA_SMEM = 218368;
    cudaFuncSetAttribute(fa, cudaFuncAttributeMaxDynamicSharedMemorySize, FA_SMEM);

    prep_w<<<4096, 256>>>(w_q, w_k, w_v, w_proj);
    prep_x<<<dim3(32, 16, 4), dim3(32, 8)>>>(x);
    qkv_f16<<<dim3(8, 4, 12), 256>>>();
    vsum_f16<<<2048, 256>>>();
    fa<<<dim3(NT / QT, NB), 256, FA_SMEM>>>(w_head);
    finalize_kernel<<<32, 256>>>(in_gamma, in_beta);
    o_epilogue<<<dim3(16, 32), 256>>>();
    proj_f16<<<dim3(8, 4, 4), 256>>>(b_proj, outF);
}